// round 1
// baseline (speedup 1.0000x reference)
#include <cuda_runtime.h>
#include <math.h>

#define HW     16384
#define IMG_H  128
#define IMG_W  128
#define BSZ    4
#define CIN    720
#define MID    512
#define NCLS   19
#define KCH    256
#define VCH    256
#define KCONV  6480   // 720*9

// ---------------- scratch (static device globals; no allocation) ----------------
__device__ float g_x    [BSZ*MID*HW];     // 134 MB  conv out -> bn/relu x (in-place) -> x+obj
__device__ float g_w3T  [KCONV*MID];      // 13 MB   transposed conv weights [k][o]
__device__ float g_qwT  [MID*KCH];        // q_w transposed [c][d]
__device__ float g_owT  [VCH*MID];        // out_w transposed [v][c]
__device__ float g_probs[BSZ*NCLS*HW];    // softmax probs [b][k][hw]
__device__ float g_S    [BSZ*NCLS];       // per-class prob sums
__device__ float g_ctx  [BSZ*NCLS*MID];   // context (unnormalized)
__device__ float g_kmat [BSZ*NCLS*KCH];
__device__ float g_vmat [BSZ*NCLS*VCH];
__device__ float g_q    [BSZ*HW*KCH];     // 67 MB  [pix][d]
__device__ float g_agg  [BSZ*VCH*HW];     // 67 MB  [b][v][hw]
__device__ float g_scale[MID];
__device__ float g_shift[MID];

// ---------------- zero small accumulators ----------------
__global__ void zero_kernel() {
    int i = blockIdx.x * 256 + threadIdx.x;
    if (i < BSZ*NCLS*MID) g_ctx[i] = 0.f;
    if (i < BSZ*NCLS)     g_S[i]   = 0.f;
}

// ---------------- transpose weights ----------------
__global__ void prep_transpose(const float* __restrict__ w3,
                               const float* __restrict__ qw,
                               const float* __restrict__ ow) {
    int i = blockIdx.x * 256 + threadIdx.x;
    if (i < MID*KCONV) {                 // w3 [o][k] -> [k][o]
        int o = i / KCONV; int k = i - o*KCONV;
        g_w3T[k*MID + o] = w3[i];
    }
    if (i < KCH*MID) {                   // q_w [d][c] -> [c][d]
        int d = i / MID; int c = i - d*MID;
        g_qwT[c*KCH + d] = qw[i];
    }
    if (i < MID*VCH) {                   // out_w [c][v] -> [v][c]
        int c = i / VCH; int v = i - c*VCH;
        g_owT[v*MID + c] = ow[i];
    }
}

// ---------------- conv3x3 as implicit GEMM: M=B*H*W, N=512, K=6480 ----------------
// block tile 128(m) x 128(n) x 8(k); 256 threads; thread tile 8x8
__global__ __launch_bounds__(256)
void conv_gemm(const float* __restrict__ feats) {
    __shared__ float As[8][128];
    __shared__ float Bs[8][128];

    int tid = threadIdx.x;
    int bn  = blockIdx.x * 128;     // output-channel base
    int by  = blockIdx.y;           // one (b,h) row of 128 pixels
    int b   = by >> 7;
    int h   = by & 127;

    const float* fb = feats + b * CIN * HW;

    int la_m = tid & 127;           // w coordinate
    int la_k = tid >> 7;            // 0..1
    int lb_n = tid & 127;
    int lb_k = tid >> 7;

    float acc[8][8];
    #pragma unroll
    for (int i = 0; i < 8; i++)
        #pragma unroll
        for (int j = 0; j < 8; j++) acc[i][j] = 0.f;

    int tx = tid & 15, ty = tid >> 4;

    for (int k0 = 0; k0 < KCONV; k0 += 8) {
        #pragma unroll
        for (int i = 0; i < 4; i++) {
            int kk = la_k + 2*i;
            int kg = k0 + kk;
            int c  = kg / 9;
            int r  = kg - c*9;
            int ky = r / 3;
            int kx = r - ky*3;
            int hh = h + ky - 1;
            int ww = la_m + kx - 1;
            float v = 0.f;
            if ((unsigned)hh < 128u && (unsigned)ww < 128u)
                v = fb[c*HW + hh*IMG_W + ww];
            As[kk][la_m] = v;
        }
        #pragma unroll
        for (int i = 0; i < 4; i++) {
            int kk = lb_k + 2*i;
            Bs[kk][lb_n] = g_w3T[(k0 + kk)*MID + bn + lb_n];
        }
        __syncthreads();
        #pragma unroll
        for (int kk = 0; kk < 8; kk++) {
            float4 a0 = *(const float4*)&As[kk][ty*8];
            float4 a1 = *(const float4*)&As[kk][ty*8+4];
            float4 b0 = *(const float4*)&Bs[kk][tx*8];
            float4 b1 = *(const float4*)&Bs[kk][tx*8+4];
            float ar[8] = {a0.x,a0.y,a0.z,a0.w,a1.x,a1.y,a1.z,a1.w};
            float br[8] = {b0.x,b0.y,b0.z,b0.w,b1.x,b1.y,b1.z,b1.w};
            #pragma unroll
            for (int i = 0; i < 8; i++)
                #pragma unroll
                for (int j = 0; j < 8; j++)
                    acc[i][j] = fmaf(ar[i], br[j], acc[i][j]);
        }
        __syncthreads();
    }

    // write x[b][n][h*128 + m], vectorized along m
    float* xb = g_x + (b*MID)*HW + h*IMG_W;
    #pragma unroll
    for (int j = 0; j < 8; j++) {
        int n = bn + tx*8 + j;
        float4 v0 = make_float4(acc[0][j], acc[1][j], acc[2][j], acc[3][j]);
        float4 v1 = make_float4(acc[4][j], acc[5][j], acc[6][j], acc[7][j]);
        *(float4*)(xb + n*HW + ty*8)     = v0;
        *(float4*)(xb + n*HW + ty*8 + 4) = v1;
    }
}

// ---------------- BN stats per channel ----------------
__global__ void bn_stats(const float* __restrict__ gamma, const float* __restrict__ beta) {
    int c = blockIdx.x, tid = threadIdx.x;
    float s = 0.f, sq = 0.f;
    for (int b = 0; b < BSZ; b++) {
        const float* p = g_x + (b*MID + c)*HW;
        for (int i = tid; i < HW; i += 256) { float v = p[i]; s += v; sq += v*v; }
    }
    __shared__ float ss[256], s2[256];
    ss[tid] = s; s2[tid] = sq; __syncthreads();
    for (int st = 128; st > 0; st >>= 1) {
        if (tid < st) { ss[tid] += ss[tid+st]; s2[tid] += s2[tid+st]; }
        __syncthreads();
    }
    if (tid == 0) {
        float n    = (float)(BSZ*HW);
        float mean = ss[0] / n;
        float var  = s2[0] / n - mean*mean;
        float rstd = rsqrtf(var + 1e-5f);
        float sc   = gamma[c] * rstd;
        g_scale[c] = sc;
        g_shift[c] = beta[c] - mean * sc;
    }
}

// ---------------- fused: BN apply + relu (in-place) + aux head + softmax + prob sums ----------------
__global__ __launch_bounds__(256)
void bn_aux_softmax(const float* __restrict__ aux_w, const float* __restrict__ aux_b,
                    float* __restrict__ aux_out) {
    __shared__ float sw[NCLS*MID];
    __shared__ float ssc[MID], ssh[MID];
    __shared__ float sb[NCLS], sS[NCLS];
    int tid = threadIdx.x;
    for (int i = tid; i < NCLS*MID; i += 256) sw[i] = aux_w[i];
    for (int i = tid; i < MID; i += 256) { ssc[i] = g_scale[i]; ssh[i] = g_shift[i]; }
    if (tid < NCLS) { sb[tid] = aux_b[tid]; sS[tid] = 0.f; }
    __syncthreads();

    int pix = blockIdx.x * 256 + tid;
    int b   = pix >> 14;
    int hw  = pix & (HW-1);
    float acc[NCLS];
    #pragma unroll
    for (int k = 0; k < NCLS; k++) acc[k] = 0.f;

    float* xb = g_x + (b*MID)*HW + hw;
    for (int c = 0; c < MID; c++) {
        float v = xb[c*HW];
        v = fmaf(v, ssc[c], ssh[c]);
        v = fmaxf(v, 0.f);
        xb[c*HW] = v;
        #pragma unroll
        for (int k = 0; k < NCLS; k++) acc[k] = fmaf(v, sw[k*MID + c], acc[k]);
    }
    float mx = -1e30f;
    #pragma unroll
    for (int k = 0; k < NCLS; k++) {
        acc[k] += sb[k];
        aux_out[(b*NCLS + k)*HW + hw] = acc[k];
        mx = fmaxf(mx, acc[k]);
    }
    float sum = 0.f;
    #pragma unroll
    for (int k = 0; k < NCLS; k++) { acc[k] = expf(acc[k] - mx); sum += acc[k]; }
    float inv = 1.f / sum;
    #pragma unroll
    for (int k = 0; k < NCLS; k++) {
        float p = acc[k] * inv;
        g_probs[(b*NCLS + k)*HW + hw] = p;
        atomicAdd(&sS[k], p);
    }
    __syncthreads();
    if (tid < NCLS) atomicAdd(&g_S[b*NCLS + tid], sS[tid]);
}

// ---------------- context: ctx[b][k][c] = sum_n probs[b][n][k] * x[b][n][c] (split over n) ----------------
__global__ __launch_bounds__(512)
void context_kernel() {
    __shared__ float pw[NCLS][512];
    int b   = blockIdx.y;
    int n0  = blockIdx.x * 512;
    int tid = threadIdx.x;        // 512 threads; tid == channel c
    for (int k = 0; k < NCLS; k++)
        pw[k][tid] = g_probs[(b*NCLS + k)*HW + n0 + tid];
    __syncthreads();

    float acc[NCLS];
    #pragma unroll
    for (int k = 0; k < NCLS; k++) acc[k] = 0.f;
    const float* xr = g_x + (b*MID + tid)*HW + n0;
    for (int n = 0; n < 512; n += 4) {
        float4 xv = *(const float4*)(xr + n);
        float vv[4] = {xv.x, xv.y, xv.z, xv.w};
        #pragma unroll
        for (int dn = 0; dn < 4; dn++) {
            float v = vv[dn];
            #pragma unroll
            for (int k = 0; k < NCLS; k++) acc[k] = fmaf(v, pw[k][n + dn], acc[k]);
        }
    }
    #pragma unroll
    for (int k = 0; k < NCLS; k++)
        atomicAdd(&g_ctx[(b*NCLS + k)*MID + tid], acc[k]);
}

// ---------------- k,v from normalized context ----------------
__global__ __launch_bounds__(256)
void kv_kernel(const float* __restrict__ k_w, const float* __restrict__ k_b,
               const float* __restrict__ v_w, const float* __restrict__ v_b) {
    int b  = blockIdx.x / NCLS;
    int kc = blockIdx.x % NCLS;
    __shared__ float ctx[MID];
    int tid = threadIdx.x;        // 256 threads; tid == d
    float S = fmaxf(g_S[b*NCLS + kc], 1e-6f);
    float invS = 1.f / S;
    for (int i = tid; i < MID; i += 256)
        ctx[i] = g_ctx[(b*NCLS + kc)*MID + i] * invS;
    __syncthreads();

    float kk = k_b[tid], vv = v_b[tid];
    const float4* kw4 = (const float4*)(k_w + tid*MID);
    const float4* vw4 = (const float4*)(v_w + tid*MID);
    for (int c4 = 0; c4 < MID/4; c4++) {
        float4 kw = kw4[c4], vw = vw4[c4];
        float c0 = ctx[c4*4], c1 = ctx[c4*4+1], c2 = ctx[c4*4+2], c3 = ctx[c4*4+3];
        kk = fmaf(c0, kw.x, fmaf(c1, kw.y, fmaf(c2, kw.z, fmaf(c3, kw.w, kk))));
        vv = fmaf(c0, vw.x, fmaf(c1, vw.y, fmaf(c2, vw.z, fmaf(c3, vw.w, vv))));
    }
    g_kmat[(b*NCLS + kc)*KCH + tid] = kk;
    g_vmat[(b*NCLS + kc)*VCH + tid] = vv;
}

// ---------------- q = x * q_w^T  (GEMM M=65536, N=256, K=512) ----------------
__global__ __launch_bounds__(256)
void gemm_q() {
    __shared__ float As[8][128];
    __shared__ float Bs[8][128];
    int tid = threadIdx.x;
    int bn = blockIdx.x * 128;
    int by = blockIdx.y;
    int b = by >> 7, h = by & 127;

    int la_m = tid & 127, la_k = tid >> 7;
    int lb_n = tid & 127, lb_k = tid >> 7;
    float acc[8][8];
    #pragma unroll
    for (int i = 0; i < 8; i++)
        #pragma unroll
        for (int j = 0; j < 8; j++) acc[i][j] = 0.f;
    int tx = tid & 15, ty = tid >> 4;

    const float* Ab = g_x + (b*MID)*HW + h*IMG_W;
    for (int k0 = 0; k0 < MID; k0 += 8) {
        #pragma unroll
        for (int i = 0; i < 4; i++) {
            int kk = la_k + 2*i;
            As[kk][la_m] = Ab[(k0 + kk)*HW + la_m];
        }
        #pragma unroll
        for (int i = 0; i < 4; i++) {
            int kk = lb_k + 2*i;
            Bs[kk][lb_n] = g_qwT[(k0 + kk)*KCH + bn + lb_n];
        }
        __syncthreads();
        #pragma unroll
        for (int kk = 0; kk < 8; kk++) {
            float4 a0 = *(const float4*)&As[kk][ty*8];
            float4 a1 = *(const float4*)&As[kk][ty*8+4];
            float4 b0 = *(const float4*)&Bs[kk][tx*8];
            float4 b1 = *(const float4*)&Bs[kk][tx*8+4];
            float ar[8] = {a0.x,a0.y,a0.z,a0.w,a1.x,a1.y,a1.z,a1.w};
            float br[8] = {b0.x,b0.y,b0.z,b0.w,b1.x,b1.y,b1.z,b1.w};
            #pragma unroll
            for (int i = 0; i < 8; i++)
                #pragma unroll
                for (int j = 0; j < 8; j++)
                    acc[i][j] = fmaf(ar[i], br[j], acc[i][j]);
        }
        __syncthreads();
    }
    // q layout [pix][d]: n-contiguous writes
    int m0 = (b << 14) + h*IMG_W;
    #pragma unroll
    for (int i = 0; i < 8; i++) {
        int m = m0 + ty*8 + i;
        float4 v0 = make_float4(acc[i][0], acc[i][1], acc[i][2], acc[i][3]);
        float4 v1 = make_float4(acc[i][4], acc[i][5], acc[i][6], acc[i][7]);
        *(float4*)(g_q + m*KCH + bn + tx*8)     = v0;
        *(float4*)(g_q + m*KCH + bn + tx*8 + 4) = v1;
    }
}

// ---------------- attention: per-pixel softmax over 19 classes, agg -> [b][v][hw] ----------------
__global__ __launch_bounds__(256)
void attention_kernel() {
    __shared__ float ks[NCLS*KCH];
    __shared__ float vs[NCLS*VCH];
    int tid = threadIdx.x;
    int pix = blockIdx.x * 256 + tid;
    int b = pix >> 14, hw = pix & (HW-1);
    for (int i = tid; i < NCLS*KCH; i += 256) ks[i] = g_kmat[b*NCLS*KCH + i];
    for (int i = tid; i < NCLS*VCH; i += 256) vs[i] = g_vmat[b*NCLS*VCH + i];
    __syncthreads();

    float s[NCLS];
    #pragma unroll
    for (int k = 0; k < NCLS; k++) s[k] = 0.f;
    const float4* qp = (const float4*)(g_q + pix*KCH);
    for (int d4 = 0; d4 < KCH/4; d4++) {
        float4 q4 = qp[d4];
        float qv[4] = {q4.x, q4.y, q4.z, q4.w};
        #pragma unroll
        for (int j = 0; j < 4; j++) {
            float q = qv[j];
            int d = d4*4 + j;
            #pragma unroll
            for (int k = 0; k < NCLS; k++) s[k] = fmaf(q, ks[k*KCH + d], s[k]);
        }
    }
    const float scale = 0.0625f;  // 1/sqrt(256)
    float mx = -1e30f;
    #pragma unroll
    for (int k = 0; k < NCLS; k++) { s[k] *= scale; mx = fmaxf(mx, s[k]); }
    float sum = 0.f;
    #pragma unroll
    for (int k = 0; k < NCLS; k++) { s[k] = expf(s[k] - mx); sum += s[k]; }
    float inv = 1.f / sum;
    #pragma unroll
    for (int k = 0; k < NCLS; k++) s[k] *= inv;

    for (int v = 0; v < VCH; v++) {
        float o = 0.f;
        #pragma unroll
        for (int k = 0; k < NCLS; k++) o = fmaf(s[k], vs[k*VCH + v], o);
        g_agg[(b*VCH + v)*HW + hw] = o;   // coalesced across threads
    }
}

// ---------------- obj = agg * out_w^T, x += obj  (GEMM M=65536, N=512, K=256) ----------------
__global__ __launch_bounds__(256)
void gemm_obj() {
    __shared__ float As[8][128];
    __shared__ float Bs[8][128];
    int tid = threadIdx.x;
    int bn = blockIdx.x * 128;
    int by = blockIdx.y;
    int b = by >> 7, h = by & 127;

    int la_m = tid & 127, la_k = tid >> 7;
    int lb_n = tid & 127, lb_k = tid >> 7;
    float acc[8][8];
    #pragma unroll
    for (int i = 0; i < 8; i++)
        #pragma unroll
        for (int j = 0; j < 8; j++) acc[i][j] = 0.f;
    int tx = tid & 15, ty = tid >> 4;

    const float* Ab = g_agg + (b*VCH)*HW + h*IMG_W;
    for (int k0 = 0; k0 < VCH; k0 += 8) {
        #pragma unroll
        for (int i = 0; i < 4; i++) {
            int kk = la_k + 2*i;
            As[kk][la_m] = Ab[(k0 + kk)*HW + la_m];
        }
        #pragma unroll
        for (int i = 0; i < 4; i++) {
            int kk = lb_k + 2*i;
            Bs[kk][lb_n] = g_owT[(k0 + kk)*MID + bn + lb_n];
        }
        __syncthreads();
        #pragma unroll
        for (int kk = 0; kk < 8; kk++) {
            float4 a0 = *(const float4*)&As[kk][ty*8];
            float4 a1 = *(const float4*)&As[kk][ty*8+4];
            float4 b0 = *(const float4*)&Bs[kk][tx*8];
            float4 b1 = *(const float4*)&Bs[kk][tx*8+4];
            float ar[8] = {a0.x,a0.y,a0.z,a0.w,a1.x,a1.y,a1.z,a1.w};
            float br[8] = {b0.x,b0.y,b0.z,b0.w,b1.x,b1.y,b1.z,b1.w};
            #pragma unroll
            for (int i = 0; i < 8; i++)
                #pragma unroll
                for (int j = 0; j < 8; j++)
                    acc[i][j] = fmaf(ar[i], br[j], acc[i][j]);
        }
        __syncthreads();
    }
    // x[b][n][hw] += acc, vectorized along m
    float* xb = g_x + (b*MID)*HW + h*IMG_W;
    #pragma unroll
    for (int j = 0; j < 8; j++) {
        int n = bn + tx*8 + j;
        float4* p0 = (float4*)(xb + n*HW + ty*8);
        float4* p1 = (float4*)(xb + n*HW + ty*8 + 4);
        float4 o0 = *p0, o1 = *p1;
        o0.x += acc[0][j]; o0.y += acc[1][j]; o0.z += acc[2][j]; o0.w += acc[3][j];
        o1.x += acc[4][j]; o1.y += acc[5][j]; o1.z += acc[6][j]; o1.w += acc[7][j];
        *p0 = o0; *p1 = o1;
    }
}

// ---------------- cls head ----------------
__global__ __launch_bounds__(256)
void cls_kernel(const float* __restrict__ cls_w, const float* __restrict__ cls_b,
                float* __restrict__ logits) {
    __shared__ float sw[NCLS*MID];
    __shared__ float sb[NCLS];
    int tid = threadIdx.x;
    for (int i = tid; i < NCLS*MID; i += 256) sw[i] = cls_w[i];
    if (tid < NCLS) sb[tid] = cls_b[tid];
    __syncthreads();

    int pix = blockIdx.x * 256 + tid;
    int b = pix >> 14, hw = pix & (HW-1);
    float acc[NCLS];
    #pragma unroll
    for (int k = 0; k < NCLS; k++) acc[k] = 0.f;
    const float* xb = g_x + (b*MID)*HW + hw;
    for (int c = 0; c < MID; c++) {
        float v = xb[c*HW];
        #pragma unroll
        for (int k = 0; k < NCLS; k++) acc[k] = fmaf(v, sw[k*MID + c], acc[k]);
    }
    #pragma unroll
    for (int k = 0; k < NCLS; k++)
        logits[(b*NCLS + k)*HW + hw] = acc[k] + sb[k];
}

// ---------------- launch ----------------
extern "C" void kernel_launch(void* const* d_in, const int* in_sizes, int n_in,
                              void* d_out, int out_size) {
    const float* feats = (const float*)d_in[0];
    const float* w3    = (const float*)d_in[1];
    const float* gamma = (const float*)d_in[2];
    const float* beta  = (const float*)d_in[3];
    const float* aux_w = (const float*)d_in[4];
    const float* aux_b = (const float*)d_in[5];
    const float* q_w   = (const float*)d_in[6];
    const float* k_w   = (const float*)d_in[7];
    const float* k_b   = (const float*)d_in[8];
    const float* v_w   = (const float*)d_in[9];
    const float* v_b   = (const float*)d_in[10];
    const float* out_w = (const float*)d_in[11];
    const float* cls_w = (const float*)d_in[12];
    const float* cls_b = (const float*)d_in[13];

    float* logits  = (float*)d_out;
    float* aux_out = (float*)d_out + BSZ*NCLS*HW;

    zero_kernel<<<(BSZ*NCLS*MID + 255)/256, 256>>>();
    prep_transpose<<<(MID*KCONV + 255)/256, 256>>>(w3, q_w, out_w);
    conv_gemm<<<dim3(MID/128, BSZ*IMG_H), 256>>>(feats);
    bn_stats<<<MID, 256>>>(gamma, beta);
    bn_aux_softmax<<<BSZ*HW/256, 256>>>(aux_w, aux_b, aux_out);
    context_kernel<<<dim3(HW/512, BSZ), 512>>>();
    kv_kernel<<<BSZ*NCLS, 256>>>(k_w, k_b, v_w, v_b);
    gemm_q<<<dim3(KCH/128, BSZ*IMG_H), 256>>>();
    attention_kernel<<<BSZ*HW/256, 256>>>();
    gemm_obj<<<dim3(MID/128, BSZ*IMG_H), 256>>>();
    cls_kernel<<<BSZ*HW/256, 256>>>(cls_w, cls_b, logits);
}

// round 3
// speedup vs baseline: 1.7888x; 1.7888x over previous
#include <cuda_runtime.h>
#include <cuda_bf16.h>
#include <math.h>
#include <cstdint>

#define HW     16384
#define IMG_H  128
#define IMG_W  128
#define BSZ    4
#define CIN    720
#define MID    512
#define NCLS   19
#define KCH    256
#define VCH    256

#define PH 130
#define PW 130

// conv tiling
#define BM        128
#define BN        128
#define KCH_C     48          // K per chunk
#define NCHUNKS   135         // 9 shifts * 15 chunks
#define ASTRIDE   56          // padded row length (bf16 elems)
#define REG_ELE   (128*ASTRIDE)          // elems per operand region
#define STAGE_ELE (4*REG_ELE)            // Ah, Al, Bh, Bl
#define STAGE_BYTES (STAGE_ELE*2)        // 57344
#define SMEM_DYN  (2*STAGE_BYTES)        // 114688

// ---------------- scratch ----------------
__device__ float g_x    [BSZ*MID*HW];
__device__ float g_qwT  [MID*KCH];
__device__ float g_owT  [VCH*MID];
__device__ float g_probs[BSZ*NCLS*HW];
__device__ float g_S    [BSZ*NCLS];
__device__ float g_ctx  [BSZ*NCLS*MID];
__device__ float g_kmat [BSZ*NCLS*KCH];
__device__ float g_vmat [BSZ*NCLS*VCH];
__device__ float g_q    [BSZ*HW*KCH];
__device__ float g_agg  [BSZ*VCH*HW];
__device__ float g_scale[MID];
__device__ float g_shift[MID];
// bf16 split buffers
__device__ __align__(16) __nv_bfloat16 g_fhi[BSZ*PH*PW*CIN];
__device__ __align__(16) __nv_bfloat16 g_flo[BSZ*PH*PW*CIN];
__device__ __align__(16) __nv_bfloat16 g_whi[9*MID*CIN];
__device__ __align__(16) __nv_bfloat16 g_wlo[9*MID*CIN];

// ---------------- helpers ----------------
__device__ __forceinline__ uint32_t smem_u32(const void* p) {
    uint32_t a;
    asm("{ .reg .u64 t; cvta.to.shared.u64 t, %1; cvt.u32.u64 %0, t; }" : "=r"(a) : "l"(p));
    return a;
}
__device__ __forceinline__ void cp16(uint32_t s, const void* g) {
    asm volatile("cp.async.cg.shared.global [%0], [%1], 16;" :: "r"(s), "l"(g));
}
__device__ __forceinline__ void cp_commit() {
    asm volatile("cp.async.commit_group;");
}
__device__ __forceinline__ void mma16816(float* d, const uint32_t* a, const uint32_t* b) {
    asm volatile(
        "mma.sync.aligned.m16n8k16.row.col.f32.bf16.bf16.f32 "
        "{%0,%1,%2,%3}, {%4,%5,%6,%7}, {%8,%9}, {%0,%1,%2,%3};"
        : "+f"(d[0]), "+f"(d[1]), "+f"(d[2]), "+f"(d[3])
        : "r"(a[0]), "r"(a[1]), "r"(a[2]), "r"(a[3]), "r"(b[0]), "r"(b[1]));
}

// ---------------- prep: zero padded bf16 buffers ----------------
__global__ void zero_pad() {
    long i = (long)blockIdx.x * 256 + threadIdx.x;
    const long n4 = (long)BSZ*PH*PW*CIN / 8;
    if (i < n4)        ((float4*)g_fhi)[i] = make_float4(0.f, 0.f, 0.f, 0.f);
    else if (i < 2*n4) ((float4*)g_flo)[i - n4] = make_float4(0.f, 0.f, 0.f, 0.f);
}

// ---------------- prep: NHWC bf16 hi/lo of feats (padded) ----------------
__global__ __launch_bounds__(256) void nhwc_prep(const float* __restrict__ feats) {
    __shared__ float tile[64][129];
    int by = blockIdx.x;            // (b,h)
    int b = by >> 7, h = by & 127;
    int tid = threadIdx.x;
    const float* fb = feats + ((long)b * CIN) * HW + h * IMG_W;
    long obase = ((long)(b * PH + h + 1) * PW + 1) * CIN;   // (h+1, w+1)
    for (int c0 = 0; c0 < CIN; c0 += 64) {
        int cw = CIN - c0; if (cw > 64) cw = 64;
        #pragma unroll 4
        for (int j = 0; j < 32; j++) {
            int idx = tid + j * 256;
            int c = idx >> 7, w = idx & 127;
            if (c < cw) tile[c][w] = fb[(long)(c0 + c) * HW + w];
        }
        __syncthreads();
        #pragma unroll 4
        for (int j = 0; j < 32; j++) {
            int idx = tid + j * 256;
            int w = idx >> 6, c = idx & 63;
            if (c < cw) {
                float v = tile[c][w];
                __nv_bfloat16 hi = __float2bfloat16(v);
                __nv_bfloat16 lo = __float2bfloat16(v - __bfloat162float(hi));
                long o = obase + (long)w * CIN + c0 + c;
                g_fhi[o] = hi;
                g_flo[o] = lo;
            }
        }
        __syncthreads();
    }
}

// ---------------- prep: weights [r][o][c] bf16 hi/lo ----------------
__global__ void w3_prep(const float* __restrict__ w3) {
    int e = blockIdx.x * 256 + threadIdx.x;
    if (e >= 9 * MID * CIN) return;
    int r = e / (MID * CIN);
    int rem = e - r * (MID * CIN);
    int o = rem / CIN;
    int c = rem - o * CIN;
    float v = w3[(o * CIN + c) * 9 + r];
    __nv_bfloat16 hi = __float2bfloat16(v);
    g_whi[e] = hi;
    g_wlo[e] = __float2bfloat16(v - __bfloat162float(hi));
}

// ---------------- zero small accumulators ----------------
__global__ void zero_kernel() {
    int i = blockIdx.x * 256 + threadIdx.x;
    if (i < BSZ*NCLS*MID) g_ctx[i] = 0.f;
    if (i < BSZ*NCLS)     g_S[i]   = 0.f;
}

// ---------------- transpose small weights ----------------
__global__ void prep_transpose(const float* __restrict__ qw, const float* __restrict__ ow) {
    int i = blockIdx.x * 256 + threadIdx.x;
    if (i < KCH*MID) {
        int d = i / MID; int c = i - d*MID;
        g_qwT[c*KCH + d] = qw[i];
    }
    if (i < MID*VCH) {
        int c = i / VCH; int v = i - c*VCH;
        g_owT[v*MID + c] = ow[i];
    }
}

// ---------------- conv3x3 via mma.sync bf16x3 ----------------
// grid (4, 512): x = 128-col output-channel block, y = (b,h). 256 threads = 8 warps (4m x 2n).
__global__ __launch_bounds__(256) void conv_mma() {
    extern __shared__ __nv_bfloat16 sm[];
    uint32_t sbase = smem_u32(sm);
    int tid = threadIdx.x;
    int lane = tid & 31, warp = tid >> 5;
    int wm = warp & 3, wn = warp >> 2;
    int qrow = lane >> 2, qcol = (lane & 3) * 2;
    int bn = blockIdx.x * BN;
    int by = blockIdx.y;
    int b = by >> 7, h = by & 127;

    const __nv_bfloat16* fhi_b = g_fhi + (long)b * PH * PW * CIN;
    const __nv_bfloat16* flo_b = g_flo + (long)b * PH * PW * CIN;

    // per-thread load mapping: 128 rows x 48 cols, 2 threads per row
    int lrow = tid >> 1, lhalf = tid & 1;
    int thr_g = lrow * CIN + lhalf * 24;                 // gmem elem offset within tile
    uint32_t thr_s = (uint32_t)(lrow * ASTRIDE + lhalf * 24) * 2;  // smem byte offset within region

    float d[2][8][4];
    #pragma unroll
    for (int mt = 0; mt < 2; mt++)
        #pragma unroll
        for (int nt = 0; nt < 8; nt++)
            #pragma unroll
            for (int e = 0; e < 4; e++) d[mt][nt][e] = 0.f;

    // chunk parameter walkers
    int r = 0, ci = 0, c0 = 0;
    int nr = 0, nci = 0, nc0 = 0;   // for prefetch (chunk it+1)

    // prologue: load chunk 0 into stage 0
    {
        int ky = 0, kx = 0;
        int ab = ((h + ky) * PW + kx) * CIN + 0 + thr_g;
        int bb = (0 * MID + bn) * CIN + 0 + thr_g;
        uint32_t st = sbase;
        #pragma unroll
        for (int j = 0; j < 3; j++) {
            cp16(st + 0*REG_ELE*2 + thr_s + j*16, fhi_b + ab + j*8);
            cp16(st + 1*REG_ELE*2 + thr_s + j*16, flo_b + ab + j*8);
            cp16(st + 2*REG_ELE*2 + thr_s + j*16, g_whi + bb + j*8);
            cp16(st + 3*REG_ELE*2 + thr_s + j*16, g_wlo + bb + j*8);
        }
        cp_commit();
    }
    nci = 1; nc0 = KCH_C;

    for (int it = 0; it < NCHUNKS; it++) {
        int s = it & 1;
        if (it + 1 < NCHUNKS) {
            int ky = nr / 3, kx = nr - ky * 3;
            int ab = ((h + ky) * PW + kx) * CIN + nc0 + thr_g;
            int bb = (nr * MID + bn) * CIN + nc0 + thr_g;
            uint32_t st = sbase + (uint32_t)(1 - s) * STAGE_BYTES;
            #pragma unroll
            for (int j = 0; j < 3; j++) {
                cp16(st + 0*REG_ELE*2 + thr_s + j*16, fhi_b + ab + j*8);
                cp16(st + 1*REG_ELE*2 + thr_s + j*16, flo_b + ab + j*8);
                cp16(st + 2*REG_ELE*2 + thr_s + j*16, g_whi + bb + j*8);
                cp16(st + 3*REG_ELE*2 + thr_s + j*16, g_wlo + bb + j*8);
            }
            cp_commit();
            nci++; nc0 += KCH_C;
            if (nci == 15) { nci = 0; nc0 = 0; nr++; }
            asm volatile("cp.async.wait_group 1;");
        } else {
            asm volatile("cp.async.wait_group 0;");
        }
        __syncthreads();

        const __nv_bfloat16* st = sm + (size_t)s * STAGE_ELE;
        const __nv_bfloat16* Ah = st;
        const __nv_bfloat16* Al = st + REG_ELE;
        const __nv_bfloat16* Bh = st + 2*REG_ELE;
        const __nv_bfloat16* Bl = st + 3*REG_ELE;

        #pragma unroll
        for (int ks = 0; ks < 3; ks++) {
            int k0 = ks * 16 + qcol;
            uint32_t ah[2][4], al[2][4], bh[8][2], bl[8][2];
            #pragma unroll
            for (int mt = 0; mt < 2; mt++) {
                int r0 = wm * 32 + mt * 16 + qrow;
                ah[mt][0] = *(const uint32_t*)(Ah + r0*ASTRIDE + k0);
                ah[mt][1] = *(const uint32_t*)(Ah + (r0+8)*ASTRIDE + k0);
                ah[mt][2] = *(const uint32_t*)(Ah + r0*ASTRIDE + k0 + 8);
                ah[mt][3] = *(const uint32_t*)(Ah + (r0+8)*ASTRIDE + k0 + 8);
                al[mt][0] = *(const uint32_t*)(Al + r0*ASTRIDE + k0);
                al[mt][1] = *(const uint32_t*)(Al + (r0+8)*ASTRIDE + k0);
                al[mt][2] = *(const uint32_t*)(Al + r0*ASTRIDE + k0 + 8);
                al[mt][3] = *(const uint32_t*)(Al + (r0+8)*ASTRIDE + k0 + 8);
            }
            #pragma unroll
            for (int nt = 0; nt < 8; nt++) {
                int n0 = wn * 64 + nt * 8 + qrow;
                bh[nt][0] = *(const uint32_t*)(Bh + n0*ASTRIDE + k0);
                bh[nt][1] = *(const uint32_t*)(Bh + n0*ASTRIDE + k0 + 8);
                bl[nt][0] = *(const uint32_t*)(Bl + n0*ASTRIDE + k0);
                bl[nt][1] = *(const uint32_t*)(Bl + n0*ASTRIDE + k0 + 8);
            }
            #pragma unroll
            for (int mt = 0; mt < 2; mt++)
                #pragma unroll
                for (int nt = 0; nt < 8; nt++) {
                    mma16816(d[mt][nt], ah[mt], bh[nt]);
                    mma16816(d[mt][nt], ah[mt], bl[nt]);
                    mma16816(d[mt][nt], al[mt], bh[nt]);
                }
        }
        __syncthreads();
        r = nr; ci = nci; c0 = nc0;   // keep walkers consistent (r unused further)
        (void)r; (void)ci; (void)c0;
    }

    // epilogue: transpose through SMEM -> coalesced stores to g_x[n][pixel]
    float* es = (float*)sm;    // [128 n][132 m]
    #pragma unroll
    for (int mt = 0; mt < 2; mt++) {
        int m = wm * 32 + mt * 16 + qrow;
        #pragma unroll
        for (int nt = 0; nt < 8; nt++) {
            int n = wn * 64 + nt * 8 + qcol;
            es[n*132 + m]       = d[mt][nt][0];
            es[(n+1)*132 + m]   = d[mt][nt][1];
            es[n*132 + m + 8]   = d[mt][nt][2];
            es[(n+1)*132 + m+8] = d[mt][nt][3];
        }
    }
    __syncthreads();
    {
        int n = tid >> 1;
        int mh = (tid & 1) * 64;
        float* dst = g_x + ((long)(b * MID + bn + n)) * HW + h * IMG_W + mh;
        const float* src = es + n*132 + mh;
        #pragma unroll
        for (int j = 0; j < 16; j++)
            ((float4*)dst)[j] = ((const float4*)src)[j];
    }
}

// ---------------- BN stats per channel ----------------
__global__ void bn_stats(const float* __restrict__ gamma, const float* __restrict__ beta) {
    int c = blockIdx.x, tid = threadIdx.x;
    float s = 0.f, sq = 0.f;
    for (int b = 0; b < BSZ; b++) {
        const float* p = g_x + (b*MID + c)*HW;
        for (int i = tid; i < HW; i += 256) { float v = p[i]; s += v; sq += v*v; }
    }
    __shared__ float ss[256], s2[256];
    ss[tid] = s; s2[tid] = sq; __syncthreads();
    for (int st = 128; st > 0; st >>= 1) {
        if (tid < st) { ss[tid] += ss[tid+st]; s2[tid] += s2[tid+st]; }
        __syncthreads();
    }
    if (tid == 0) {
        float n    = (float)(BSZ*HW);
        float mean = ss[0] / n;
        float var  = s2[0] / n - mean*mean;
        float rstd = rsqrtf(var + 1e-5f);
        float sc   = gamma[c] * rstd;
        g_scale[c] = sc;
        g_shift[c] = beta[c] - mean * sc;
    }
}

// ---------------- fused: BN apply + relu + aux head + softmax + prob sums ----------------
__global__ __launch_bounds__(256)
void bn_aux_softmax(const float* __restrict__ aux_w, const float* __restrict__ aux_b,
                    float* __restrict__ aux_out) {
    __shared__ float sw[NCLS*MID];
    __shared__ float ssc[MID], ssh[MID];
    __shared__ float sb[NCLS], sS[NCLS];
    int tid = threadIdx.x;
    for (int i = tid; i < NCLS*MID; i += 256) sw[i] = aux_w[i];
    for (int i = tid; i < MID; i += 256) { ssc[i] = g_scale[i]; ssh[i] = g_shift[i]; }
    if (tid < NCLS) { sb[tid] = aux_b[tid]; sS[tid] = 0.f; }
    __syncthreads();

    int pix = blockIdx.x * 256 + tid;
    int b   = pix >> 14;
    int hw  = pix & (HW-1);
    float acc[NCLS];
    #pragma unroll
    for (int k = 0; k < NCLS; k++) acc[k] = 0.f;

    float* xb = g_x + (b*MID)*HW + hw;
    for (int c = 0; c < MID; c++) {
        float v = xb[c*HW];
        v = fmaf(v, ssc[c], ssh[c]);
        v = fmaxf(v, 0.f);
        xb[c*HW] = v;
        #pragma unroll
        for (int k = 0; k < NCLS; k++) acc[k] = fmaf(v, sw[k*MID + c], acc[k]);
    }
    float mx = -1e30f;
    #pragma unroll
    for (int k = 0; k < NCLS; k++) {
        acc[k] += sb[k];
        aux_out[(b*NCLS + k)*HW + hw] = acc[k];
        mx = fmaxf(mx, acc[k]);
    }
    float sum = 0.f;
    #pragma unroll
    for (int k = 0; k < NCLS; k++) { acc[k] = expf(acc[k] - mx); sum += acc[k]; }
    float inv = 1.f / sum;
    #pragma unroll
    for (int k = 0; k < NCLS; k++) {
        float p = acc[k] * inv;
        g_probs[(b*NCLS + k)*HW + hw] = p;
        atomicAdd(&sS[k], p);
    }
    __syncthreads();
    if (tid < NCLS) atomicAdd(&g_S[b*NCLS + tid], sS[tid]);
}

// ---------------- context ----------------
__global__ __launch_bounds__(512)
void context_kernel() {
    __shared__ float pw[NCLS][512];
    int b   = blockIdx.y;
    int n0  = blockIdx.x * 512;
    int tid = threadIdx.x;
    for (int k = 0; k < NCLS; k++)
        pw[k][tid] = g_probs[(b*NCLS + k)*HW + n0 + tid];
    __syncthreads();

    float acc[NCLS];
    #pragma unroll
    for (int k = 0; k < NCLS; k++) acc[k] = 0.f;
    const float* xr = g_x + (b*MID + tid)*HW + n0;
    for (int n = 0; n < 512; n += 4) {
        float4 xv = *(const float4*)(xr + n);
        float vv[4] = {xv.x, xv.y, xv.z, xv.w};
        #pragma unroll
        for (int dn = 0; dn < 4; dn++) {
            float v = vv[dn];
            #pragma unroll
            for (int k = 0; k < NCLS; k++) acc[k] = fmaf(v, pw[k][n + dn], acc[k]);
        }
    }
    #pragma unroll
    for (int k = 0; k < NCLS; k++)
        atomicAdd(&g_ctx[(b*NCLS + k)*MID + tid], acc[k]);
}

// ---------------- k,v from normalized context ----------------
__global__ __launch_bounds__(256)
void kv_kernel(const float* __restrict__ k_w, const float* __restrict__ k_b,
               const float* __restrict__ v_w, const float* __restrict__ v_b) {
    int b  = blockIdx.x / NCLS;
    int kc = blockIdx.x % NCLS;
    __shared__ float ctx[MID];
    int tid = threadIdx.x;
    float S = fmaxf(g_S[b*NCLS + kc], 1e-6f);
    float invS = 1.f / S;
    for (int i = tid; i < MID; i += 256)
        ctx[i] = g_ctx[(b*NCLS + kc)*MID + i] * invS;
    __syncthreads();

    float kk = k_b[tid], vv = v_b[tid];
    const float4* kw4 = (const float4*)(k_w + tid*MID);
    const float4* vw4 = (const float4*)(v_w + tid*MID);
    for (int c4 = 0; c4 < MID/4; c4++) {
        float4 kw = kw4[c4], vw = vw4[c4];
        float c0 = ctx[c4*4], c1 = ctx[c4*4+1], c2 = ctx[c4*4+2], c3 = ctx[c4*4+3];
        kk = fmaf(c0, kw.x, fmaf(c1, kw.y, fmaf(c2, kw.z, fmaf(c3, kw.w, kk))));
        vv = fmaf(c0, vw.x, fmaf(c1, vw.y, fmaf(c2, vw.z, fmaf(c3, vw.w, vv))));
    }
    g_kmat[(b*NCLS + kc)*KCH + tid] = kk;
    g_vmat[(b*NCLS + kc)*VCH + tid] = vv;
}

// ---------------- q = x * q_w^T ----------------
__global__ __launch_bounds__(256)
void gemm_q() {
    __shared__ float As[8][128];
    __shared__ float Bs[8][128];
    int tid = threadIdx.x;
    int bn = blockIdx.x * 128;
    int by = blockIdx.y;
    int b = by >> 7, h = by & 127;

    int la_m = tid & 127, la_k = tid >> 7;
    int lb_n = tid & 127, lb_k = tid >> 7;
    float acc[8][8];
    #pragma unroll
    for (int i = 0; i < 8; i++)
        #pragma unroll
        for (int j = 0; j < 8; j++) acc[i][j] = 0.f;
    int tx = tid & 15, ty = tid >> 4;

    const float* Ab = g_x + (b*MID)*HW + h*IMG_W;
    for (int k0 = 0; k0 < MID; k0 += 8) {
        #pragma unroll
        for (int i = 0; i < 4; i++) {
            int kk = la_k + 2*i;
            As[kk][la_m] = Ab[(k0 + kk)*HW + la_m];
        }
        #pragma unroll
        for (int i = 0; i < 4; i++) {
            int kk = lb_k + 2*i;
            Bs[kk][lb_n] = g_qwT[(k0 + kk)*KCH + bn + lb_n];
        }
        __syncthreads();
        #pragma unroll
        for (int kk = 0; kk < 8; kk++) {
            float4 a0 = *(const float4*)&As[kk][ty*8];
            float4 a1 = *(const float4*)&As[kk][ty*8+4];
            float4 b0 = *(const float4*)&Bs[kk][tx*8];
            float4 b1 = *(const float4*)&Bs[kk][tx*8+4];
            float ar[8] = {a0.x,a0.y,a0.z,a0.w,a1.x,a1.y,a1.z,a1.w};
            float br[8] = {b0.x,b0.y,b0.z,b0.w,b1.x,b1.y,b1.z,b1.w};
            #pragma unroll
            for (int i = 0; i < 8; i++)
                #pragma unroll
                for (int j = 0; j < 8; j++)
                    acc[i][j] = fmaf(ar[i], br[j], acc[i][j]);
        }
        __syncthreads();
    }
    int m0 = (b << 14) + h*IMG_W;
    #pragma unroll
    for (int i = 0; i < 8; i++) {
        int m = m0 + ty*8 + i;
        float4 v0 = make_float4(acc[i][0], acc[i][1], acc[i][2], acc[i][3]);
        float4 v1 = make_float4(acc[i][4], acc[i][5], acc[i][6], acc[i][7]);
        *(float4*)(g_q + m*KCH + bn + tx*8)     = v0;
        *(float4*)(g_q + m*KCH + bn + tx*8 + 4) = v1;
    }
}

// ---------------- attention ----------------
__global__ __launch_bounds__(256)
void attention_kernel() {
    __shared__ float ks[NCLS*KCH];
    __shared__ float vs[NCLS*VCH];
    int tid = threadIdx.x;
    int pix = blockIdx.x * 256 + tid;
    int b = pix >> 14, hw = pix & (HW-1);
    for (int i = tid; i < NCLS*KCH; i += 256) ks[i] = g_kmat[b*NCLS*KCH + i];
    for (int i = tid; i < NCLS*VCH; i += 256) vs[i] = g_vmat[b*NCLS*VCH + i];
    __syncthreads();

    float s[NCLS];
    #pragma unroll
    for (int k = 0; k < NCLS; k++) s[k] = 0.f;
    const float4* qp = (const float4*)(g_q + (long)pix*KCH);
    for (int d4 = 0; d4 < KCH/4; d4++) {
        float4 q4 = qp[d4];
        float qv[4] = {q4.x, q4.y, q4.z, q4.w};
        #pragma unroll
        for (int j = 0; j < 4; j++) {
            float q = qv[j];
            int d = d4*4 + j;
            #pragma unroll
            for (int k = 0; k < NCLS; k++) s[k] = fmaf(q, ks[k*KCH + d], s[k]);
        }
    }
    const float scale = 0.0625f;
    float mx = -1e30f;
    #pragma unroll
    for (int k = 0; k < NCLS; k++) { s[k] *= scale; mx = fmaxf(mx, s[k]); }
    float sum = 0.f;
    #pragma unroll
    for (int k = 0; k < NCLS; k++) { s[k] = expf(s[k] - mx); sum += s[k]; }
    float inv = 1.f / sum;
    #pragma unroll
    for (int k = 0; k < NCLS; k++) s[k] *= inv;

    for (int v = 0; v < VCH; v++) {
        float o = 0.f;
        #pragma unroll
        for (int k = 0; k < NCLS; k++) o = fmaf(s[k], vs[k*VCH + v], o);
        g_agg[(b*VCH + v)*HW + hw] = o;
    }
}

// ---------------- obj = agg * out_w^T, x += obj ----------------
__global__ __launch_bounds__(256)
void gemm_obj() {
    __shared__ float As[8][128];
    __shared__ float Bs[8][128];
    int tid = threadIdx.x;
    int bn = blockIdx.x * 128;
    int by = blockIdx.y;
    int b = by >> 7, h = by & 127;

    int la_m = tid & 127, la_k = tid >> 7;
    int lb_n = tid & 127, lb_k = tid >> 7;
    float acc[8][8];
    #pragma unroll
    for (int i = 0; i < 8; i++)
        #pragma unroll
        for (int j = 0; j < 8; j++) acc[i][j] = 0.f;
    int tx = tid & 15, ty = tid >> 4;

    const float* Ab = g_agg + (b*VCH)*HW + h*IMG_W;
    for (int k0 = 0; k0 < VCH; k0 += 8) {
        #pragma unroll
        for (int i = 0; i < 4; i++) {
            int kk = la_k + 2*i;
            As[kk][la_m] = Ab[(k0 + kk)*HW + la_m];
        }
        #pragma unroll
        for (int i = 0; i < 4; i++) {
            int kk = lb_k + 2*i;
            Bs[kk][lb_n] = g_owT[(k0 + kk)*MID + bn + lb_n];
        }
        __syncthreads();
        #pragma unroll
        for (int kk = 0; kk < 8; kk++) {
            float4 a0 = *(const float4*)&As[kk][ty*8];
            float4 a1 = *(const float4*)&As[kk][ty*8+4];
            float4 b0 = *(const float4*)&Bs[kk][tx*8];
            float4 b1 = *(const float4*)&Bs[kk][tx*8+4];
            float ar[8] = {a0.x,a0.y,a0.z,a0.w,a1.x,a1.y,a1.z,a1.w};
            float br[8] = {b0.x,b0.y,b0.z,b0.w,b1.x,b1.y,b1.z,b1.w};
            #pragma unroll
            for (int i = 0; i < 8; i++)
                #pragma unroll
                for (int j = 0; j < 8; j++)
                    acc[i][j] = fmaf(ar[i], br[j], acc[i][j]);
        }
        __syncthreads();
    }
    float* xb = g_x + (b*MID)*HW + h*IMG_W;
    #pragma unroll
    for (int j = 0; j < 8; j++) {
        int n = bn + tx*8 + j;
        float4* p0 = (float4*)(xb + n*HW + ty*8);
        float4* p1 = (float4*)(xb + n*HW + ty*8 + 4);
        float4 o0 = *p0, o1 = *p1;
        o0.x += acc[0][j]; o0.y += acc[1][j]; o0.z += acc[2][j]; o0.w += acc[3][j];
        o1.x += acc[4][j]; o1.y += acc[5][j]; o1.z += acc[6][j]; o1.w += acc[7][j];
        *p0 = o0; *p1 = o1;
    }
}

// ---------------- cls head ----------------
__global__ __launch_bounds__(256)
void cls_kernel(const float* __restrict__ cls_w, const float* __restrict__ cls_b,
                float* __restrict__ logits) {
    __shared__ float sw[NCLS*MID];
    __shared__ float sb[NCLS];
    int tid = threadIdx.x;
    for (int i = tid; i < NCLS*MID; i += 256) sw[i] = cls_w[i];
    if (tid < NCLS) sb[tid] = cls_b[tid];
    __syncthreads();

    int pix = blockIdx.x * 256 + tid;
    int b = pix >> 14, hw = pix & (HW-1);
    float acc[NCLS];
    #pragma unroll
    for (int k = 0; k < NCLS; k++) acc[k] = 0.f;
    const float* xb = g_x + (b*MID)*HW + hw;
    for (int c = 0; c < MID; c++) {
        float v = xb[c*HW];
        #pragma unroll
        for (int k = 0; k < NCLS; k++) acc[k] = fmaf(v, sw[k*MID + c], acc[k]);
    }
    #pragma unroll
    for (int k = 0; k < NCLS; k++)
        logits[(b*NCLS + k)*HW + hw] = acc[k] + sb[k];
}

// ---------------- launch ----------------
extern "C" void kernel_launch(void* const* d_in, const int* in_sizes, int n_in,
                              void* d_out, int out_size) {
    const float* feats = (const float*)d_in[0];
    const float* w3    = (const float*)d_in[1];
    const float* gamma = (const float*)d_in[2];
    const float* beta  = (const float*)d_in[3];
    const float* aux_w = (const float*)d_in[4];
    const float* aux_b = (const float*)d_in[5];
    const float* q_w   = (const float*)d_in[6];
    const float* k_w   = (const float*)d_in[7];
    const float* k_b   = (const float*)d_in[8];
    const float* v_w   = (const float*)d_in[9];
    const float* v_b   = (const float*)d_in[10];
    const float* out_w = (const float*)d_in[11];
    const float* cls_w = (const float*)d_in[12];
    const float* cls_b = (const float*)d_in[13];

    float* logits  = (float*)d_out;
    float* aux_out = (float*)d_out + BSZ*NCLS*HW;

    cudaFuncSetAttribute(conv_mma, cudaFuncAttributeMaxDynamicSharedMemorySize, SMEM_DYN);

    long pad4 = 2L * ((long)BSZ*PH*PW*CIN / 8);
    zero_pad<<<(int)((pad4 + 255) / 256), 256>>>();
    nhwc_prep<<<BSZ*IMG_H, 256>>>(feats);
    w3_prep<<<(9*MID*CIN + 255)/256, 256>>>(w3);
    prep_transpose<<<(MID*VCH + 255)/256, 256>>>(q_w, out_w);
    zero_kernel<<<(BSZ*NCLS*MID + 255)/256, 256>>>();
    conv_mma<<<dim3(MID/BN, BSZ*IMG_H), 256, SMEM_DYN>>>();
    bn_stats<<<MID, 256>>>(gamma, beta);
    bn_aux_softmax<<<BSZ*HW/256, 256>>>(aux_w, aux_b, aux_out);
    context_kernel<<<dim3(HW/512, BSZ), 512>>>();
    kv_kernel<<<BSZ*NCLS, 256>>>(k_w, k_b, v_w, v_b);
    gemm_q<<<dim3(KCH/128, BSZ*IMG_H), 256>>>();
    attention_kernel<<<BSZ*HW/256, 256>>>();
    gemm_obj<<<dim3(MID/128, BSZ*IMG_H), 256>>>();
    cls_kernel<<<BSZ*HW/256, 256>>>(cls_w, cls_b, logits);
}